// round 7
// baseline (speedup 1.0000x reference)
#include <cuda_runtime.h>

#define NPIX (512*512)
#define D1B 6
#define D1S 3
#define MAXMB (D1B*NPIX+1)
#define MAXMS (D1S*NPIX+1)
#define ALPHA_B (32.0f/33.0f)
#define ALPHA_S 0.8f
#define BI_COMPAT 10.0f
#define SP_COMPAT 3.0f
#define TPB 256

// float4 tables for the Q filtering (3-buffer ping-pong per lattice).
__device__ float4 g_tb[3][MAXMB];
__device__ float4 g_ts[3][MAXMS];
// fp32 scalar tables for the prologue ones-filter (2-buffer ping-pong).
__device__ float  g_sb[2][MAXMB];
__device__ float  g_ss[2][MAXMS];
// Composed 2-pass neighbor indices: bilateral pairs (0,1),(2,3),(4,5); spatial pair (0,1).
__device__ int    g_cb[3][(size_t)(MAXMB - 1) * 8];
__device__ int    g_cs9[(size_t)(MAXMS - 1) * 8];
__device__ float4 g_msgS[NPIX];   // precomputed spatial message (scaled)
__device__ float  g_inb[NPIX];
__device__ float  g_ins[NPIX];

__device__ __forceinline__ void red4(float4* p, float x, float y, float z, float w) {
    asm volatile("red.global.add.v4.f32 [%0], {%1,%2,%3,%4};"
                 :: "l"(p), "f"(x), "f"(y), "f"(z), "f"(w) : "memory");
}
__device__ __forceinline__ void red1(float* p, float v) {
    asm volatile("red.global.add.f32 [%0], %1;" :: "l"(p), "f"(v) : "memory");
}

__device__ __forceinline__ float4 softmax_neg(float4 u, float4 msg) {
    float zx = msg.x - u.x, zy = msg.y - u.y, zz = msg.z - u.z, zw = msg.w - u.w;
    float m = fmaxf(fmaxf(zx, zy), fmaxf(zz, zw));
    float ex = __expf(zx - m), ey = __expf(zy - m), ez = __expf(zz - m), ew = __expf(zw - m);
    float inv = 1.0f / (ex + ey + ez + ew);
    return make_float4(ex * inv, ey * inv, ez * inv, ew * inv);
}

// Build composed 2-pass stencils; also zero the scalar splat buffers for this replay.
__global__ void __launch_bounds__(TPB) compose(const int2* __restrict__ bnb, int Mb,
                                               const int2* __restrict__ bns, int Ms) {
    int t = blockIdx.x * blockDim.x + threadIdx.x;
    if (t <= Mb) g_sb[0][t] = 0.f;
    if (t <= Ms) g_ss[0][t] = 0.f;
    if (t < Mb) {
#pragma unroll
        for (int p = 0; p < 3; p++) {
            const int2* r1 = bnb + (size_t)(2 * p) * Mb;
            const int2* r2 = bnb + (size_t)(2 * p + 1) * Mb;
            int2 ab = r1[t];
            int2 nn = r2[t];
            int o3 = 0, o4 = 0, o6 = 0, o7 = 0;
            if (nn.x > 0) { int2 c = r1[nn.x - 1]; o3 = c.x; o4 = c.y; }
            if (nn.y > 0) { int2 c = r1[nn.y - 1]; o6 = c.x; o7 = c.y; }
            int4* dst = (int4*)&g_cb[p][(size_t)t * 8];
            dst[0] = make_int4(ab.x, ab.y, nn.x, o3);
            dst[1] = make_int4(o4, nn.y, o6, o7);
        }
    } else {
        int m = t - Mb;
        if (m < Ms) {
            const int2* r1 = bns;
            const int2* r2 = bns + (size_t)Ms;
            int2 ab = r1[m];
            int2 nn = r2[m];
            int o3 = 0, o4 = 0, o6 = 0, o7 = 0;
            if (nn.x > 0) { int2 c = r1[nn.x - 1]; o3 = c.x; o4 = c.y; }
            if (nn.y > 0) { int2 c = r1[nn.y - 1]; o6 = c.x; o7 = c.y; }
            int4* dst = (int4*)&g_cs9[(size_t)m * 8];
            dst[0] = make_int4(ab.x, ab.y, nn.x, o3);
            dst[1] = make_int4(o4, nn.y, o6, o7);
        }
    }
}

__device__ __forceinline__ float4 gather9(const int* __restrict__ idx8,
                                          const float4* __restrict__ s, int center) {
    int4 i0 = *(const int4*)(idx8);
    int4 i1 = *(const int4*)(idx8 + 4);
    float4 c  = s[center];
    float4 a0 = s[i0.x], a1 = s[i0.y];
    float4 n1 = s[i0.z], n1a = s[i0.w], n1b = s[i1.x];
    float4 n2 = s[i1.y], n2a = s[i1.z], n2b = s[i1.w];
    float4 r;
    r.x = c.x + 0.5f * (a0.x + a1.x + n1.x + n2.x) + 0.25f * (n1a.x + n1b.x + n2a.x + n2b.x);
    r.y = c.y + 0.5f * (a0.y + a1.y + n1.y + n2.y) + 0.25f * (n1a.y + n1b.y + n2a.y + n2b.y);
    r.z = c.z + 0.5f * (a0.z + a1.z + n1.z + n2.z) + 0.25f * (n1a.z + n1b.z + n2a.z + n2b.z);
    r.w = c.w + 0.5f * (a0.w + a1.w + n1.w + n2.w) + 0.25f * (n1a.w + n1b.w + n2a.w + n2b.w);
    return r;
}

__device__ __forceinline__ float gather9s(const int* __restrict__ idx8,
                                          const float* __restrict__ s, int center) {
    int4 i0 = *(const int4*)(idx8);
    int4 i1 = *(const int4*)(idx8 + 4);
    return s[center]
         + 0.5f  * (s[i0.x] + s[i0.y] + s[i0.z] + s[i1.y])
         + 0.25f * (s[i0.w] + s[i1.x] + s[i1.z] + s[i1.w]);
}

// ---------------- Prologue (scalar ones-filter) ----------------

__global__ void __launch_bounds__(TPB) splat_ones_s(
        const int* __restrict__ osb, const float* __restrict__ wsb,
        const int* __restrict__ oss, const float* __restrict__ wss) {
    int n = blockIdx.x * blockDim.x + threadIdx.x;
    if (n >= NPIX) return;
#pragma unroll
    for (int r = 0; r < D1B; r++)
        red1(&g_sb[0][osb[n * D1B + r]], wsb[n * D1B + r]);
#pragma unroll
    for (int r = 0; r < D1S; r++)
        red1(&g_ss[0][oss[n * D1S + r]], wss[n * D1S + r]);
}

// pk1: bilateral composed (0,1): sb0->sb1 ; spatial composed (0,1): ss0->ss1
__global__ void __launch_bounds__(TPB) pk1(int Mb, int Ms) {
    int t = blockIdx.x * blockDim.x + threadIdx.x;
    if (t < Mb) {
        g_sb[1][t + 1] = gather9s(&g_cb[0][(size_t)t * 8], g_sb[0], t + 1);
        if (t == 0) g_sb[1][0] = 0.f;
    } else {
        int m = t - Mb;
        if (m < Ms) {
            g_ss[1][m + 1] = gather9s(&g_cs9[(size_t)m * 8], g_ss[0], m + 1);
            if (m == 0) g_ss[1][0] = 0.f;
        }
    }
}

// pk2: bilateral composed (2,3): sb1->sb0 ; spatial simple pass 2: ss1->ss0.
// Also zeros float4 splat buffers tb0/ts0 for the Q0 splat.
__global__ void __launch_bounds__(TPB) pk2(int Mb, const int2* __restrict__ bns, int Ms) {
    int t = blockIdx.x * blockDim.x + threadIdx.x;
    if (t < Mb) {
        g_sb[0][t + 1] = gather9s(&g_cb[1][(size_t)t * 8], g_sb[1], t + 1);
        g_tb[0][t + 1] = make_float4(0.f, 0.f, 0.f, 0.f);
        if (t == 0) { g_sb[0][0] = 0.f; g_tb[0][0] = make_float4(0.f, 0.f, 0.f, 0.f); }
    } else {
        int m = t - Mb;
        if (m < Ms) {
            int2 nb = bns[(size_t)2 * Ms + m];
            const float* __restrict__ s = g_ss[1];
            g_ss[0][m + 1] = s[m + 1] + 0.5f * (s[nb.x] + s[nb.y]);
            g_ts[0][m + 1] = make_float4(0.f, 0.f, 0.f, 0.f);
            if (m == 0) { g_ss[0][0] = 0.f; g_ts[0][0] = make_float4(0.f, 0.f, 0.f, 0.f); }
        }
    }
}

// pk3: bilateral composed (4,5): sb0->sb1 (final bilateral ones in sb1; spatial final in ss0)
__global__ void __launch_bounds__(TPB) pk3(int Mb) {
    int t = blockIdx.x * blockDim.x + threadIdx.x;
    if (t >= Mb) return;
    g_sb[1][t + 1] = gather9s(&g_cb[2][(size_t)t * 8], g_sb[0], t + 1);
    if (t == 0) g_sb[1][0] = 0.f;
}

// Norms + Q0 init + Q0 splat (float4 tables zeroed by pk2).
__global__ void __launch_bounds__(TPB) norm_slice_init(
        const float4* __restrict__ unary,
        const int* __restrict__ osb, const float* __restrict__ wsb,
        const int* __restrict__ oss, const float* __restrict__ wss) {
    int n = blockIdx.x * blockDim.x + threadIdx.x;
    if (n >= NPIX) return;
    float sb = 0.f;
#pragma unroll
    for (int r = 0; r < D1B; r++)
        sb += g_sb[1][osb[n * D1B + r]] * wsb[n * D1B + r];
    g_inb[n] = 1.0f / (ALPHA_B * sb + 1e-20f);
    float ss = 0.f;
#pragma unroll
    for (int r = 0; r < D1S; r++)
        ss += g_ss[0][oss[n * D1S + r]] * wss[n * D1S + r];
    g_ins[n] = 1.0f / (ALPHA_S * ss + 1e-20f);
    float4 q = softmax_neg(unary[n], make_float4(0.f, 0.f, 0.f, 0.f));
#pragma unroll
    for (int r = 0; r < D1B; r++) {
        int o = osb[n * D1B + r];
        float w = wsb[n * D1B + r];
        red4(&g_tb[0][o], q.x * w, q.y * w, q.z * w, q.w * w);
    }
#pragma unroll
    for (int r = 0; r < D1S; r++) {
        int o = oss[n * D1S + r];
        float w = wss[n * D1S + r];
        red4(&g_ts[0][o], q.x * w, q.y * w, q.z * w, q.w * w);
    }
}

// ---------------- Per-round kernels ----------------

// K1: bilateral composed (0,1): tb0->tb1 ; spatial composed (0,1): ts0->ts1
__global__ void __launch_bounds__(TPB) k1(int Mb, int Ms) {
    int t = blockIdx.x * blockDim.x + threadIdx.x;
    if (t < Mb) {
        g_tb[1][t + 1] = gather9(&g_cb[0][(size_t)t * 8], g_tb[0], t + 1);
        if (t == 0) g_tb[1][0] = make_float4(0.f, 0.f, 0.f, 0.f);
    } else {
        int m = t - Mb;
        if (m < Ms) {
            g_ts[1][m + 1] = gather9(&g_cs9[(size_t)m * 8], g_ts[0], m + 1);
            if (m == 0) g_ts[1][0] = make_float4(0.f, 0.f, 0.f, 0.f);
        }
    }
}

// K2: bilateral composed (2,3): tb1->tb2 ; spatial simple pass 2: ts1->ts2; zero tb0/ts0.
__global__ void __launch_bounds__(TPB) k2(int Mb, const int2* __restrict__ bns, int Ms) {
    int t = blockIdx.x * blockDim.x + threadIdx.x;
    if (t < Mb) {
        g_tb[2][t + 1] = gather9(&g_cb[1][(size_t)t * 8], g_tb[1], t + 1);
        g_tb[0][t + 1] = make_float4(0.f, 0.f, 0.f, 0.f);
        if (t == 0) {
            g_tb[2][0] = make_float4(0.f, 0.f, 0.f, 0.f);
            g_tb[0][0] = make_float4(0.f, 0.f, 0.f, 0.f);
        }
    } else {
        int m = t - Mb;
        if (m < Ms) {
            int2 nb = bns[(size_t)2 * Ms + m];
            const float4* __restrict__ s = g_ts[1];
            float4 c = s[m + 1], a = s[nb.x], b = s[nb.y];
            g_ts[2][m + 1] = make_float4(c.x + 0.5f * (a.x + b.x), c.y + 0.5f * (a.y + b.y),
                                         c.z + 0.5f * (a.z + b.z), c.w + 0.5f * (a.w + b.w));
            g_ts[0][m + 1] = make_float4(0.f, 0.f, 0.f, 0.f);
            if (m == 0) {
                g_ts[2][0] = make_float4(0.f, 0.f, 0.f, 0.f);
                g_ts[0][0] = make_float4(0.f, 0.f, 0.f, 0.f);
            }
        }
    }
}

// K3x: bilateral composed (4,5): tb2->tb1, AND compute spatial message per pixel
// (ts2 is final after k2). Independent jobs share the grid for latency overlap.
__global__ void __launch_bounds__(TPB) k3x(int Mb,
        const int* __restrict__ oss, const float* __restrict__ wss) {
    int t = blockIdx.x * blockDim.x + threadIdx.x;
    if (t < Mb) {
        g_tb[1][t + 1] = gather9(&g_cb[2][(size_t)t * 8], g_tb[2], t + 1);
        if (t == 0) g_tb[1][0] = make_float4(0.f, 0.f, 0.f, 0.f);
    }
    if (t < NPIX) {
        float4 fs = make_float4(0.f, 0.f, 0.f, 0.f);
#pragma unroll
        for (int r = 0; r < D1S; r++) {
            int o = oss[t * D1S + r];
            float w = wss[t * D1S + r];
            float4 v = g_ts[2][o];
            fs.x += v.x * w; fs.y += v.y * w; fs.z += v.z * w; fs.w += v.w * w;
        }
        float cs = SP_COMPAT * ALPHA_S * g_ins[t];
        g_msgS[t] = make_float4(fs.x * cs, fs.y * cs, fs.z * cs, fs.w * cs);
    }
}

// Slice bilateral + precomputed spatial msg + softmax + splat next Q (or write out).
__global__ void __launch_bounds__(TPB) slice_mf(
        const float4* __restrict__ unary,
        const int* __restrict__ osb, const float* __restrict__ wsb,
        const int* __restrict__ oss, const float* __restrict__ wss,
        float4* __restrict__ outp, int write_out) {
    int n = blockIdx.x * blockDim.x + threadIdx.x;
    if (n >= NPIX) return;
    float4 fb = make_float4(0.f, 0.f, 0.f, 0.f);
    int   ob[D1B];
    float wb[D1B];
#pragma unroll
    for (int r = 0; r < D1B; r++) {
        ob[r] = osb[n * D1B + r];
        wb[r] = wsb[n * D1B + r];
        float4 v = g_tb[1][ob[r]];
        fb.x += v.x * wb[r]; fb.y += v.y * wb[r]; fb.z += v.z * wb[r]; fb.w += v.w * wb[r];
    }
    float cb = BI_COMPAT * ALPHA_B * g_inb[n];
    float4 ms = g_msgS[n];
    float4 msg = make_float4(fb.x * cb + ms.x, fb.y * cb + ms.y,
                             fb.z * cb + ms.z, fb.w * cb + ms.w);
    float4 q = softmax_neg(unary[n], msg);
    if (write_out) {
        outp[n] = q;
    } else {
#pragma unroll
        for (int r = 0; r < D1B; r++)
            red4(&g_tb[0][ob[r]], q.x * wb[r], q.y * wb[r], q.z * wb[r], q.w * wb[r]);
#pragma unroll
        for (int r = 0; r < D1S; r++) {
            int o = oss[n * D1S + r];
            float w = wss[n * D1S + r];
            red4(&g_ts[0][o], q.x * w, q.y * w, q.z * w, q.w * w);
        }
    }
}

extern "C" void kernel_launch(void* const* d_in, const int* in_sizes, int n_in,
                              void* d_out, int out_size) {
    const float4* unary = (const float4*)d_in[0];
    const float*  wsb   = (const float*)d_in[1];
    const int*    osb   = (const int*)d_in[2];
    const int2*   bnb   = (const int2*)d_in[3];
    const float*  wss   = (const float*)d_in[5];
    const int*    oss   = (const int*)d_in[6];
    const int2*   bns   = (const int2*)d_in[7];

    int Mb = in_sizes[3] / (D1B * 2);   // blur_neighbors_bilateral: [6, Mb, 2]
    int Ms = in_sizes[7] / (D1S * 2);   // blur_neighbors_spatial:   [3, Ms, 2]

    const int nblk = (NPIX + TPB - 1) / TPB;
    const int cblk = (Mb + Ms + TPB - 1) / TPB;
    const int bblk = (Mb + TPB - 1) / TPB;
    int maxT = (Mb > NPIX ? Mb : NPIX);
    const int xblk = (maxT + TPB - 1) / TPB;

    // ---- Prologue: scalar ones-filter for norms, Q0 init + splat ----
    compose<<<cblk, TPB>>>(bnb, Mb, bns, Ms);
    splat_ones_s<<<nblk, TPB>>>(osb, wsb, oss, wss);
    pk1<<<cblk, TPB>>>(Mb, Ms);
    pk2<<<cblk, TPB>>>(Mb, bns, Ms);
    pk3<<<bblk, TPB>>>(Mb);
    norm_slice_init<<<nblk, TPB>>>(unary, osb, wsb, oss, wss);

    // ---- 10 mean-field iterations ----
    for (int it = 0; it < 10; it++) {
        k1<<<cblk, TPB>>>(Mb, Ms);
        k2<<<cblk, TPB>>>(Mb, bns, Ms);
        k3x<<<xblk, TPB>>>(Mb, oss, wss);
        slice_mf<<<nblk, TPB>>>(unary, osb, wsb, oss, wss,
                                (float4*)d_out, it == 9 ? 1 : 0);
    }
}